// round 2
// baseline (speedup 1.0000x reference)
#include <cuda_runtime.h>
#include <cstdint>

// out[src] += edge_attr[e] * x[dst]   (E=1.6M, N=100k, D=32)
// Inputs (metadata order): edge_index int32 [2,E] (JAX downcasts int64->int32),
//                          edge_attr f32 [E], x f32 [N,32]
// Output: f32 [N,32]

__global__ void zero_out_kernel(float4* __restrict__ out, int n4) {
    int i = blockIdx.x * blockDim.x + threadIdx.x;
    int stride = gridDim.x * blockDim.x;
    float4 z = make_float4(0.f, 0.f, 0.f, 0.f);
    for (; i < n4; i += stride) out[i] = z;
}

__global__ void scatter_kernel(const int* __restrict__ edge_index,
                               const float* __restrict__ edge_attr,
                               const float* __restrict__ x,
                               float* __restrict__ out,
                               int E) {
    // Each warp handles 32 edges. Lanes cooperatively load the edge stream
    // (coalesced), then iterate the 32 edges via shfl broadcast; per edge,
    // lane = feature index -> coalesced 128B gather + 128B REDG.
    int lane = threadIdx.x & 31;
    int warp = (blockIdx.x * blockDim.x + threadIdx.x) >> 5;
    int base = warp * 32;
    if (base >= E) return;

    int e = base + lane;
    int src = 0, dst = 0;
    float a = 0.0f;
    if (e < E) {
        src = __ldg(&edge_index[e]);        // row 0: src
        dst = __ldg(&edge_index[E + e]);    // row 1: dst
        a   = __ldg(&edge_attr[e]);
    }

    int cnt = min(32, E - base);
    if (cnt == 32) {
        #pragma unroll 8
        for (int i = 0; i < 32; i++) {
            int   s  = __shfl_sync(0xffffffffu, src, i);
            int   d  = __shfl_sync(0xffffffffu, dst, i);
            float aa = __shfl_sync(0xffffffffu, a,   i);
            float v = aa * __ldg(&x[(long)d * 32 + lane]);
            atomicAdd(&out[(long)s * 32 + lane], v);
        }
    } else {
        for (int i = 0; i < cnt; i++) {
            int   s  = __shfl_sync(0xffffffffu, src, i);
            int   d  = __shfl_sync(0xffffffffu, dst, i);
            float aa = __shfl_sync(0xffffffffu, a,   i);
            float v = aa * __ldg(&x[(long)d * 32 + lane]);
            atomicAdd(&out[(long)s * 32 + lane], v);
        }
    }
}

extern "C" void kernel_launch(void* const* d_in, const int* in_sizes, int n_in,
                              void* d_out, int out_size) {
    const int*   edge_index = (const int*)d_in[0];
    const float* edge_attr  = (const float*)d_in[1];
    const float* x          = (const float*)d_in[2];
    float*       out        = (float*)d_out;

    int E = in_sizes[0] / 2;

    // zero the (poisoned) output
    int n4 = out_size / 4;
    int zt = 256;
    int zb = (n4 + zt - 1) / zt;
    if (zb > 8192) zb = 8192;
    zero_out_kernel<<<zb, zt>>>((float4*)out, n4);

    // 32 edges per warp
    int warps = (E + 31) / 32;
    int threads = 256;                       // 8 warps/block
    int blocks = (warps * 32 + threads - 1) / threads;
    scatter_kernel<<<blocks, threads>>>(edge_index, edge_attr, x, out, E);
}

// round 3
// speedup vs baseline: 1.0462x; 1.0462x over previous
#include <cuda_runtime.h>
#include <cstdint>

// out[src] += edge_attr[e] * x[dst]   (E=1.6M, N=100k, D=32)
// Inputs: edge_index int32 [2,E], edge_attr f32 [E], x f32 [N,32]
// Output: f32 [N,32]

__global__ void zero_out_kernel(float4* __restrict__ out, int n4) {
    int i = blockIdx.x * blockDim.x + threadIdx.x;
    int stride = gridDim.x * blockDim.x;
    float4 z = make_float4(0.f, 0.f, 0.f, 0.f);
    for (; i < n4; i += stride) out[i] = z;
}

__device__ __forceinline__ void red_add_v4(float* addr, float4 v) {
    asm volatile("red.global.add.v4.f32 [%0], {%1, %2, %3, %4};"
                 :: "l"(addr), "f"(v.x), "f"(v.y), "f"(v.z), "f"(v.w)
                 : "memory");
}

// Warp = 4 edge-slots x 8 lanes; each lane covers 4 features (float4).
// 32 edges per warp, 8 unrolled iterations of 4 edges each.
#define EDGES_PER_WARP 32

__global__ void scatter_kernel(const int* __restrict__ edge_index,
                               const float* __restrict__ edge_attr,
                               const float* __restrict__ x,
                               float* __restrict__ out,
                               int E) {
    int lane = threadIdx.x & 31;
    int slot = lane >> 3;            // 0..3  : which edge in the group of 4
    int fofs = (lane & 7) << 2;      // 0..28 : feature offset (float index)
    int warp = (blockIdx.x * blockDim.x + threadIdx.x) >> 5;
    int base = warp * EDGES_PER_WARP;
    if (base >= E) return;

    if (base + EDGES_PER_WARP <= E) {
        #pragma unroll
        for (int i = 0; i < EDGES_PER_WARP / 4; i++) {
            int e   = base + i * 4 + slot;
            int src = __ldg(&edge_index[e]);       // 4 consecutive ints, 1 sector
            int dst = __ldg(&edge_index[E + e]);
            float a = __ldg(&edge_attr[e]);
            float4 v = *(const float4*)(x + (long)dst * 32 + fofs);
            v.x *= a; v.y *= a; v.z *= a; v.w *= a;
            red_add_v4(out + (long)src * 32 + fofs, v);
        }
    } else {
        for (int i = 0; i < EDGES_PER_WARP / 4; i++) {
            int e = base + i * 4 + slot;
            if (e < E) {
                int src = __ldg(&edge_index[e]);
                int dst = __ldg(&edge_index[E + e]);
                float a = __ldg(&edge_attr[e]);
                float4 v = *(const float4*)(x + (long)dst * 32 + fofs);
                v.x *= a; v.y *= a; v.z *= a; v.w *= a;
                red_add_v4(out + (long)src * 32 + fofs, v);
            }
        }
    }
}

extern "C" void kernel_launch(void* const* d_in, const int* in_sizes, int n_in,
                              void* d_out, int out_size) {
    const int*   edge_index = (const int*)d_in[0];
    const float* edge_attr  = (const float*)d_in[1];
    const float* x          = (const float*)d_in[2];
    float*       out        = (float*)d_out;

    int E = in_sizes[0] / 2;

    // zero the (poisoned) output
    int n4 = out_size / 4;
    int zt = 256;
    int zb = (n4 + zt - 1) / zt;
    if (zb > 8192) zb = 8192;
    zero_out_kernel<<<zb, zt>>>((float4*)out, n4);

    // 32 edges per warp
    int warps  = (E + EDGES_PER_WARP - 1) / EDGES_PER_WARP;
    int threads = 256;                         // 8 warps/block
    int blocks = (warps * 32 + threads - 1) / threads;
    scatter_kernel<<<blocks, threads>>>(edge_index, edge_attr, x, out, E);
}